// round 15
// baseline (speedup 1.0000x reference)
#include <cuda_runtime.h>
#include <cstdint>

// TopologyTracker: 64x64 histogram of (prev, curr) transitions over 16.7M events.
// Output layout (float32): [0..4095] = transitions + counts, [4096] = total + N.
//
// R15: workload is pinned to the smem-ATOMS floor (1 lane/event; hist =
// 26.6us ncu across 1/2/3-CTA/SM configs). Remaining variable is the
// timed-loop tail spread, which shrinks monotonically with warps/SM
// (delta total-hist: 4.7us @16w -> 2.5us @32w -> 0.6us @48w). This round:
// 4 CTAs/SM x 512 (64 warps/SM). The 8-ev/iter core needs exactly 32 regs
// = the cap at 2048 thr/SM, so no register cliff (unlike the 16-ev core).
// Wrapper: graph memset node zeroes out; CTA 0 folds trans_in/total into
// its flush; flush staggered per CTA across L2 lines.

#define NUM_TILES 64
#define NUM_BINS  (NUM_TILES * NUM_TILES)   // 4096
#define THREADS   512
#define GRID      592                        // 4 CTAs/SM * 148 SMs

__global__ void __launch_bounds__(THREADS, 4)
tt_hist(const int* __restrict__ prev,
        const int* __restrict__ curr,
        const float* __restrict__ trans_in,
        const float* __restrict__ total_in,
        float* __restrict__ out,
        int out_size,
        int n)
{
    __shared__ int h[NUM_BINS];

    #pragma unroll
    for (int i = threadIdx.x; i < NUM_BINS; i += THREADS) {
        h[i] = 0;
    }
    __syncthreads();

    const int tid    = blockIdx.x * THREADS + threadIdx.x;
    const int stride = gridDim.x * THREADS;

    const int4* __restrict__ p4 = reinterpret_cast<const int4*>(prev);
    const int4* __restrict__ c4 = reinterpret_cast<const int4*>(curr);

    // 8 events per iteration: 4 front-batched 16B loads (2 per stream).
    const int n8 = n >> 3;
    for (int i = tid; i < n8; i += stride) {
        int4 pa = p4[2 * i];
        int4 pb = p4[2 * i + 1];
        int4 ca = c4[2 * i];
        int4 cb = c4[2 * i + 1];

        atomicAdd(&h[(pa.x << 6) + ca.x], 1);
        atomicAdd(&h[(pa.y << 6) + ca.y], 1);
        atomicAdd(&h[(pa.z << 6) + ca.z], 1);
        atomicAdd(&h[(pa.w << 6) + ca.w], 1);
        atomicAdd(&h[(pb.x << 6) + cb.x], 1);
        atomicAdd(&h[(pb.y << 6) + cb.y], 1);
        atomicAdd(&h[(pb.z << 6) + cb.z], 1);
        atomicAdd(&h[(pb.w << 6) + cb.w], 1);
    }

    // Scalar tail (n % 8; N = 16777216 divisible, kept for safety).
    for (int i = (n8 << 3) + tid; i < n; i += stride) {
        atomicAdd(&h[(prev[i] << 6) + curr[i]], 1);
    }

    __syncthreads();

    // Flush onto memset-zeroed out; staggered start per CTA so concurrent
    // CTAs hit different 128B L2 lines. CTA 0 folds in trans_in (must not
    // skip zero-count bins) and the total scalar.
    const int off = (blockIdx.x << 5) & (NUM_BINS - 1);
    if (blockIdx.x == 0) {
        #pragma unroll
        for (int j = threadIdx.x; j < NUM_BINS; j += THREADS) {
            int i = (j + off) & (NUM_BINS - 1);
            atomicAdd(&out[i], (float)h[i] + trans_in[i]);
        }
        if (threadIdx.x == 0 && NUM_BINS < out_size) {
            atomicAdd(&out[NUM_BINS], total_in[0] + (float)n);
        }
    } else {
        #pragma unroll
        for (int j = threadIdx.x; j < NUM_BINS; j += THREADS) {
            int i = (j + off) & (NUM_BINS - 1);
            int v = h[i];
            if (v != 0) {
                atomicAdd(&out[i], (float)v);
            }
        }
    }
}

// ---------------------------------------------------------------------------
// Launcher: memset node zeroes out, then one hist kernel does everything.
// ---------------------------------------------------------------------------
extern "C" void kernel_launch(void* const* d_in, const int* in_sizes, int n_in,
                              void* d_out, int out_size)
{
    const int*   prev     = (const int*)  d_in[0];
    const int*   curr     = (const int*)  d_in[1];
    const float* trans_in = (const float*)d_in[2];
    const float* total_in = (const float*)d_in[3];
    float*       out      = (float*)d_out;

    const int n = in_sizes[0];

    // Zero the output (graph-capturable memset node).
    cudaMemsetAsync(d_out, 0, (size_t)out_size * sizeof(float), 0);

    tt_hist<<<GRID, THREADS>>>(prev, curr, trans_in, total_in, out,
                               out_size, n);
}

// round 16
// speedup vs baseline: 1.0748x; 1.0748x over previous
#include <cuda_runtime.h>
#include <cstdint>

// TopologyTracker: 64x64 histogram of (prev, curr) transitions over 16.7M events.
// Output layout (float32): [0..4095] = transitions + counts, [4096] = total + N.
//
// FINAL (== R14, the measured optimum at 27.2us):
//   - Hot loop: LDG.128 + smem ATOMS, 1 atomic lane/event. This sits on the
//     smem-atomic/LSU dispatch floor (2 lanes/cyc/SM -> 26.6us hist),
//     reproduced identically across 1/2/3-CTA/SM configs. All alternatives
//     (L2 REDG offload x3 variants, non-atomic warp-private RMW,
//     work-stealing, grid-barrier finalize, 4-CTA/SM) measured slower.
//   - Config: 444 CTAs x 512 threads (3 CTAs/SM, 24 warps/SM) minimizes the
//     timed-loop tail spread (total-hist delta: 3.2/2.5/0.6/2.1us for
//     1/2/3/4 CTAs/SM). 8 ev/iter core fits in 32 regs -> no register cliff.
//   - Wrapper: graph memset node zeroes out; CTA 0 folds trans_in + total
//     into its flush; flush staggered per CTA across 128B L2 lines.
//   - Exactness: all counts are integers < 2^24 added to integer-valued
//     floats -> float accumulation is exact and order-independent.

#define NUM_TILES 64
#define NUM_BINS  (NUM_TILES * NUM_TILES)   // 4096
#define THREADS   512
#define GRID      444                        // 3 CTAs/SM * 148 SMs

__global__ void __launch_bounds__(THREADS, 3)
tt_hist(const int* __restrict__ prev,
        const int* __restrict__ curr,
        const float* __restrict__ trans_in,
        const float* __restrict__ total_in,
        float* __restrict__ out,
        int out_size,
        int n)
{
    __shared__ int h[NUM_BINS];

    #pragma unroll
    for (int i = threadIdx.x; i < NUM_BINS; i += THREADS) {
        h[i] = 0;
    }
    __syncthreads();

    const int tid    = blockIdx.x * THREADS + threadIdx.x;
    const int stride = gridDim.x * THREADS;

    const int4* __restrict__ p4 = reinterpret_cast<const int4*>(prev);
    const int4* __restrict__ c4 = reinterpret_cast<const int4*>(curr);

    // 8 events per iteration: 4 front-batched 16B loads (2 per stream).
    const int n8 = n >> 3;
    for (int i = tid; i < n8; i += stride) {
        int4 pa = p4[2 * i];
        int4 pb = p4[2 * i + 1];
        int4 ca = c4[2 * i];
        int4 cb = c4[2 * i + 1];

        atomicAdd(&h[(pa.x << 6) + ca.x], 1);
        atomicAdd(&h[(pa.y << 6) + ca.y], 1);
        atomicAdd(&h[(pa.z << 6) + ca.z], 1);
        atomicAdd(&h[(pa.w << 6) + ca.w], 1);
        atomicAdd(&h[(pb.x << 6) + cb.x], 1);
        atomicAdd(&h[(pb.y << 6) + cb.y], 1);
        atomicAdd(&h[(pb.z << 6) + cb.z], 1);
        atomicAdd(&h[(pb.w << 6) + cb.w], 1);
    }

    // Scalar tail (n % 8; N = 16777216 divisible, kept for safety).
    for (int i = (n8 << 3) + tid; i < n; i += stride) {
        atomicAdd(&h[(prev[i] << 6) + curr[i]], 1);
    }

    __syncthreads();

    // Flush onto memset-zeroed out; staggered start per CTA so concurrent
    // CTAs hit different 128B L2 lines. CTA 0 folds in trans_in (must not
    // skip zero-count bins) and the total scalar.
    const int off = (blockIdx.x << 5) & (NUM_BINS - 1);
    if (blockIdx.x == 0) {
        #pragma unroll
        for (int j = threadIdx.x; j < NUM_BINS; j += THREADS) {
            int i = (j + off) & (NUM_BINS - 1);
            atomicAdd(&out[i], (float)h[i] + trans_in[i]);
        }
        if (threadIdx.x == 0 && NUM_BINS < out_size) {
            atomicAdd(&out[NUM_BINS], total_in[0] + (float)n);
        }
    } else {
        #pragma unroll
        for (int j = threadIdx.x; j < NUM_BINS; j += THREADS) {
            int i = (j + off) & (NUM_BINS - 1);
            int v = h[i];
            if (v != 0) {
                atomicAdd(&out[i], (float)v);
            }
        }
    }
}

// ---------------------------------------------------------------------------
// Launcher: memset node zeroes out, then one hist kernel does everything.
// ---------------------------------------------------------------------------
extern "C" void kernel_launch(void* const* d_in, const int* in_sizes, int n_in,
                              void* d_out, int out_size)
{
    const int*   prev     = (const int*)  d_in[0];
    const int*   curr     = (const int*)  d_in[1];
    const float* trans_in = (const float*)d_in[2];
    const float* total_in = (const float*)d_in[3];
    float*       out      = (float*)d_out;

    const int n = in_sizes[0];

    // Zero the output (graph-capturable memset node).
    cudaMemsetAsync(d_out, 0, (size_t)out_size * sizeof(float), 0);

    tt_hist<<<GRID, THREADS>>>(prev, curr, trans_in, total_in, out,
                               out_size, n);
}